// round 2
// baseline (speedup 1.0000x reference)
#include <cuda_runtime.h>
#include <math.h>

#define ROWS      32768
#define CCH       1024
#define NB        8
#define BLKW      128
#define LAMBDA_F  0.01f
#define INV_SQRTC (1.0f / 32.0f)

// ---------------- scratch (device globals; no allocation allowed) ------------
__device__ float g_xr[(size_t)ROWS * CCH];   // 128 MB
__device__ float g_xi[(size_t)ROWS * CCH];   // 128 MB
__device__ float g_o1r[(size_t)ROWS * CCH];  // 128 MB
__device__ float g_o1i[(size_t)ROWS * CCH];  // 128 MB

// ---------------- forward FFT: real input, ortho norm ------------------------
// Stockham radix-2, 10 stages, 512 threads = 1 butterfly/thread/stage.
__global__ void fft_fwd_kernel(const float* __restrict__ x,
                               float* __restrict__ outr,
                               float* __restrict__ outi) {
    __shared__ float ar[CCH], ai[CCH], br[CCH], bi[CCH];
    __shared__ float twr[CCH / 2], twi[CCH / 2];
    const int t = threadIdx.x;                 // 0..511
    const size_t row = blockIdx.x;
    const float* xp = x + row * CCH;

    ar[t]        = xp[t]        * INV_SQRTC;
    ar[t + 512]  = xp[t + 512]  * INV_SQRTC;
    ai[t]        = 0.0f;
    ai[t + 512]  = 0.0f;
    float s, c;
    sincosf(-6.283185307179586f * (float)t / 1024.0f, &s, &c);
    twr[t] = c; twi[t] = s;
    __syncthreads();

    float *pr = ar, *pi = ai, *qr = br, *qi = bi;
    #pragma unroll
    for (int m = 1; m <= 512; m <<= 1) {
        const int k    = t & (m - 1);
        const int widx = t - k;                // (t/m)*m
        const float wr = twr[widx], wi = twi[widx];
        const float c0r = pr[t],       c0i = pi[t];
        const float c1r = pr[t + 512], c1i = pi[t + 512];
        const int o = 2 * t - k;
        qr[o]     = c0r + c1r;
        qi[o]     = c0i + c1i;
        const float dr = c0r - c1r, di = c0i - c1i;
        qr[o + m] = wr * dr - wi * di;
        qi[o + m] = wr * di + wi * dr;
        __syncthreads();
        float* tp;
        tp = pr; pr = qr; qr = tp;
        tp = pi; pi = qi; qi = tp;
    }
    outr[row * CCH + t]       = pr[t];
    outr[row * CCH + t + 512] = pr[t + 512];
    outi[row * CCH + t]       = pi[t];
    outi[row * CCH + t + 512] = pi[t + 512];
}

// ---------------- inverse FFT (real part) + residual -------------------------
__global__ void fft_inv_kernel(const float* __restrict__ inr,
                               const float* __restrict__ ini,
                               const float* __restrict__ xres,
                               float* __restrict__ out) {
    __shared__ float ar[CCH], ai[CCH], br[CCH], bi[CCH];
    __shared__ float twr[CCH / 2], twi[CCH / 2];
    const int t = threadIdx.x;
    const size_t row = blockIdx.x;

    ar[t]       = inr[row * CCH + t];
    ar[t + 512] = inr[row * CCH + t + 512];
    ai[t]       = ini[row * CCH + t];
    ai[t + 512] = ini[row * CCH + t + 512];
    float s, c;
    sincosf(6.283185307179586f * (float)t / 1024.0f, &s, &c);  // conj twiddles
    twr[t] = c; twi[t] = s;
    __syncthreads();

    float *pr = ar, *pi = ai, *qr = br, *qi = bi;
    #pragma unroll
    for (int m = 1; m <= 512; m <<= 1) {
        const int k    = t & (m - 1);
        const int widx = t - k;
        const float wr = twr[widx], wi = twi[widx];
        const float c0r = pr[t],       c0i = pi[t];
        const float c1r = pr[t + 512], c1i = pi[t + 512];
        const int o = 2 * t - k;
        qr[o]     = c0r + c1r;
        qi[o]     = c0i + c1i;
        const float dr = c0r - c1r, di = c0i - c1i;
        qr[o + m] = wr * dr - wi * di;
        qi[o + m] = wr * di + wi * dr;
        __syncthreads();
        float* tp;
        tp = pr; pr = qr; qr = tp;
        tp = pi; pi = qi; qi = tp;
    }
    out[row * CCH + t]       = pr[t]       * INV_SQRTC + xres[row * CCH + t];
    out[row * CCH + t + 512] = pr[t + 512] * INV_SQRTC + xres[row * CCH + t + 512];
}

// ---------------- block-diagonal complex MLP layer (tiled fp32 GEMM) ---------
// grid = (ROWS/64, NB), block = 256 threads.
// Each CTA: one 128x128 complex weight block in smem + 64-row input tile.
// Thread (lane, warp): computes 8 rows x 4 cols complex accumulator tile.
__device__ __forceinline__ float softshrink_f(float v) {
    return (v > LAMBDA_F) ? (v - LAMBDA_F) : ((v < -LAMBDA_F) ? (v + LAMBDA_F) : 0.0f);
}

template <bool RELU, bool SHRINK>
__global__ void mlp_layer_kernel(const float* __restrict__ Ar,
                                 const float* __restrict__ Ai,
                                 const float* __restrict__ Wg,   // [2][8][128][128]
                                 const float* __restrict__ Bg,   // [2][8][128]
                                 float* __restrict__ Or,
                                 float* __restrict__ Oi) {
    extern __shared__ float sm[];
    float* sWr = sm;                      // 16384 floats
    float* sWi = sm + 16384;              // 16384
    float* sXr = sm + 32768;              // 64*128 = 8192
    float* sXi = sm + 40960;              // 8192
    float* sBr = sm + 49152;              // 128
    float* sBi = sm + 49280;              // 128

    const int tid = threadIdx.x;          // 0..255
    const int blk = blockIdx.y;
    const int m0  = blockIdx.x * 64;

    const float* wr_g = Wg + (size_t)blk * (BLKW * BLKW);
    const float* wi_g = Wg + (size_t)(NB + blk) * (BLKW * BLKW);
    for (int idx = tid; idx < BLKW * BLKW; idx += 256) {
        sWr[idx] = wr_g[idx];
        sWi[idx] = wi_g[idx];
    }
    for (int idx = tid; idx < 64 * BLKW; idx += 256) {
        const int r  = idx >> 7;
        const int cc = idx & 127;
        const size_t g = (size_t)(m0 + r) * CCH + (size_t)blk * BLKW + cc;
        sXr[idx] = Ar[g];
        sXi[idx] = Ai[g];
    }
    if (tid < BLKW) {
        sBr[tid] = Bg[blk * BLKW + tid];
        sBi[tid] = Bg[NB * BLKW + blk * BLKW + tid];
    }
    __syncthreads();

    const int lane = tid & 31;
    const int wrp  = tid >> 5;
    const int r0   = wrp * 8;
    const int c0   = lane * 4;

    float aR[8][4], aI[8][4];
    #pragma unroll
    for (int r = 0; r < 8; r++)
        #pragma unroll
        for (int q = 0; q < 4; q++) { aR[r][q] = 0.0f; aI[r][q] = 0.0f; }

    const float4* sWr4 = (const float4*)sWr;
    const float4* sWi4 = (const float4*)sWi;

    for (int kk = 0; kk < BLKW; kk++) {
        const float4 w_r = sWr4[kk * 32 + lane];
        const float4 w_i = sWi4[kk * 32 + lane];
        #pragma unroll
        for (int r = 0; r < 8; r++) {
            const float xr = sXr[(r0 + r) * BLKW + kk];
            const float xi = sXi[(r0 + r) * BLKW + kk];
            aR[r][0] += xr * w_r.x;  aR[r][0] -= xi * w_i.x;
            aI[r][0] += xi * w_r.x;  aI[r][0] += xr * w_i.x;
            aR[r][1] += xr * w_r.y;  aR[r][1] -= xi * w_i.y;
            aI[r][1] += xi * w_r.y;  aI[r][1] += xr * w_i.y;
            aR[r][2] += xr * w_r.z;  aR[r][2] -= xi * w_i.z;
            aI[r][2] += xi * w_r.z;  aI[r][2] += xr * w_i.z;
            aR[r][3] += xr * w_r.w;  aR[r][3] -= xi * w_i.w;
            aI[r][3] += xi * w_r.w;  aI[r][3] += xr * w_i.w;
        }
    }

    const float4 bR = *(const float4*)&sBr[c0];
    const float4 bI = *(const float4*)&sBi[c0];
    const float bRv[4] = {bR.x, bR.y, bR.z, bR.w};
    const float bIv[4] = {bI.x, bI.y, bI.z, bI.w};

    #pragma unroll
    for (int r = 0; r < 8; r++) {
        float4 oR, oI;
        float vR[4], vI[4];
        #pragma unroll
        for (int q = 0; q < 4; q++) {
            float vr = aR[r][q] + bRv[q];
            float vi = aI[r][q] + bIv[q];
            if (RELU)  { vr = fmaxf(vr, 0.0f); vi = fmaxf(vi, 0.0f); }
            if (SHRINK){ vr = softshrink_f(vr); vi = softshrink_f(vi); }
            vR[q] = vr; vI[q] = vi;
        }
        oR.x = vR[0]; oR.y = vR[1]; oR.z = vR[2]; oR.w = vR[3];
        oI.x = vI[0]; oI.y = vI[1]; oI.z = vI[2]; oI.w = vI[3];
        const size_t g = (size_t)(m0 + r0 + r) * CCH + (size_t)blk * BLKW + c0;
        *(float4*)&Or[g] = oR;
        *(float4*)&Oi[g] = oI;
    }
}

// ---------------------------------------------------------------------------
extern "C" void kernel_launch(void* const* d_in, const int* in_sizes, int n_in,
                              void* d_out, int out_size) {
    (void)in_sizes; (void)n_in; (void)out_size;
    const float* x  = (const float*)d_in[0];
    const float* w1 = (const float*)d_in[1];
    const float* b1 = (const float*)d_in[2];
    const float* w2 = (const float*)d_in[3];
    const float* b2 = (const float*)d_in[4];
    float* out = (float*)d_out;

    float *xr, *xi, *o1r, *o1i;
    cudaGetSymbolAddress((void**)&xr,  g_xr);
    cudaGetSymbolAddress((void**)&xi,  g_xi);
    cudaGetSymbolAddress((void**)&o1r, g_o1r);
    cudaGetSymbolAddress((void**)&o1i, g_o1i);

    const int SMEM_BYTES = (49152 + 256) * (int)sizeof(float);  // 197632 B
    cudaFuncSetAttribute(mlp_layer_kernel<true, false>,
                         cudaFuncAttributeMaxDynamicSharedMemorySize, SMEM_BYTES);
    cudaFuncSetAttribute(mlp_layer_kernel<false, true>,
                         cudaFuncAttributeMaxDynamicSharedMemorySize, SMEM_BYTES);

    // 1) forward FFT
    fft_fwd_kernel<<<ROWS, 512>>>(x, xr, xi);

    // 2) layer 1 (relu)
    dim3 grid(ROWS / 64, NB);
    mlp_layer_kernel<true, false><<<grid, 256, SMEM_BYTES>>>(xr, xi, w1, b1, o1r, o1i);

    // 3) layer 2 (softshrink) -> back into xr/xi
    mlp_layer_kernel<false, true><<<grid, 256, SMEM_BYTES>>>(o1r, o1i, w2, b2, xr, xi);

    // 4) inverse FFT + residual
    fft_inv_kernel<<<ROWS, 512>>>(xr, xi, x, out);
}

// round 4
// speedup vs baseline: 2.8651x; 2.8651x over previous
#include <cuda_runtime.h>
#include <cuda_bf16.h>
#include <math.h>
#include <stdint.h>

#define ROWS      32768
#define CCH       1024
#define NB        8
#define BLKW      128
#define KPAD      136            // padded halves per smem row (272 B, conflict-free)
#define LAMBDA_F  0.01f
#define INV_SQRTC (1.0f / 32.0f)

// ------------------------- scratch (device globals) -------------------------
__device__ __align__(128) __nv_bfloat16 g_xr [(size_t)NB * ROWS * BLKW]; // blocked [blk][row][128]
__device__ __align__(128) __nv_bfloat16 g_xi [(size_t)NB * ROWS * BLKW];
__device__ __align__(128) __nv_bfloat16 g_o1r[(size_t)NB * ROWS * BLKW];
__device__ __align__(128) __nv_bfloat16 g_o1i[(size_t)NB * ROWS * BLKW];
// converted weights, [blk][n][k] bf16
__device__ __align__(128) __nv_bfloat16 g_w1r[NB * BLKW * BLKW];
__device__ __align__(128) __nv_bfloat16 g_w1i[NB * BLKW * BLKW];
__device__ __align__(128) __nv_bfloat16 g_w2r[NB * BLKW * BLKW];
__device__ __align__(128) __nv_bfloat16 g_w2i[NB * BLKW * BLKW];

// ------------------------- weight conversion --------------------------------
__global__ void convert_weights(const float* __restrict__ w1,
                                const float* __restrict__ w2,
                                __nv_bfloat16* __restrict__ W1r, __nv_bfloat16* __restrict__ W1i,
                                __nv_bfloat16* __restrict__ W2r, __nv_bfloat16* __restrict__ W2i) {
    int idx = blockIdx.x * blockDim.x + threadIdx.x;   // dst layout [blk][n][k]
    if (idx >= NB * BLKW * BLKW) return;
    int blk = idx >> 14;
    int n   = (idx >> 7) & 127;
    int k   = idx & 127;
    size_t src = (size_t)blk * (BLKW * BLKW) + (size_t)k * BLKW + n;  // w[.][blk][k][n]
    W1r[idx] = __float2bfloat16(w1[src]);
    W1i[idx] = __float2bfloat16(w1[(size_t)NB * BLKW * BLKW + src]);
    W2r[idx] = __float2bfloat16(w2[src]);
    W2i[idx] = __float2bfloat16(w2[(size_t)NB * BLKW * BLKW + src]);
}

// ------------------------- radix-4 Stockham FFT ------------------------------
__global__ __launch_bounds__(256) void fft_fwd_kernel(const float* __restrict__ x,
                                                      __nv_bfloat16* __restrict__ outr,
                                                      __nv_bfloat16* __restrict__ outi) {
    __shared__ float ar[CCH], ai[CCH], br[CCH], bi[CCH];
    __shared__ float twr[CCH], twi[CCH];
    const int t = threadIdx.x;              // 0..255
    const size_t row = blockIdx.x;
    const float* xp = x + row * CCH;

    #pragma unroll
    for (int q = 0; q < 4; q++) {
        int pos = t + 256 * q;
        ar[pos] = xp[pos] * INV_SQRTC;
        ai[pos] = 0.0f;
        float s, c;
        sincosf(-6.283185307179586f * (float)pos / 1024.0f, &s, &c);
        twr[pos] = c; twi[pos] = s;
    }
    __syncthreads();

    float *pr = ar, *pi = ai, *qr = br, *qi = bi;
    #pragma unroll
    for (int p = 1; p <= 256; p <<= 2) {
        const int k = t & (p - 1);
        const int j = ((t - k) << 2) + k;
        const int a1 = k * (256 / p);
        float u0r = pr[t],       u0i = pi[t];
        float x1r = pr[t + 256], x1i = pi[t + 256];
        float x2r = pr[t + 512], x2i = pi[t + 512];
        float x3r = pr[t + 768], x3i = pi[t + 768];
        float w1r = twr[a1],     w1i = twi[a1];
        float w2r = twr[2 * a1], w2i = twi[2 * a1];
        float w3r = twr[3 * a1], w3i = twi[3 * a1];
        float u1r = x1r * w1r - x1i * w1i, u1i = x1r * w1i + x1i * w1r;
        float u2r = x2r * w2r - x2i * w2i, u2i = x2r * w2i + x2i * w2r;
        float u3r = x3r * w3r - x3i * w3i, u3i = x3r * w3i + x3i * w3r;
        float v0r = u0r + u2r, v0i = u0i + u2i;
        float v1r = u0r - u2r, v1i = u0i - u2i;
        float v2r = u1r + u3r, v2i = u1i + u3i;
        float v3r = u1i - u3i, v3i = u3r - u1r;   // -i*(u1-u3)
        __syncthreads();
        qr[j]         = v0r + v2r;  qi[j]         = v0i + v2i;
        qr[j + p]     = v1r + v3r;  qi[j + p]     = v1i + v3i;
        qr[j + 2 * p] = v0r - v2r;  qi[j + 2 * p] = v0i - v2i;
        qr[j + 3 * p] = v1r - v3r;  qi[j + 3 * p] = v1i - v3i;
        __syncthreads();
        float* tp;
        tp = pr; pr = qr; qr = tp;
        tp = pi; pi = qi; qi = tp;
    }

    #pragma unroll
    for (int q = 0; q < 4; q++) {
        int pos = t + 256 * q;
        int blk = pos >> 7, col = pos & 127;
        size_t g = ((size_t)blk * ROWS + row) * BLKW + col;
        outr[g] = __float2bfloat16(pr[pos]);
        outi[g] = __float2bfloat16(pi[pos]);
    }
}

__global__ __launch_bounds__(256) void fft_inv_kernel(const __nv_bfloat16* __restrict__ inr,
                                                      const __nv_bfloat16* __restrict__ ini,
                                                      const float* __restrict__ xres,
                                                      float* __restrict__ out) {
    __shared__ float ar[CCH], ai[CCH], br[CCH], bi[CCH];
    __shared__ float twr[CCH], twi[CCH];
    const int t = threadIdx.x;
    const size_t row = blockIdx.x;

    #pragma unroll
    for (int q = 0; q < 4; q++) {
        int pos = t + 256 * q;
        int blk = pos >> 7, col = pos & 127;
        size_t g = ((size_t)blk * ROWS + row) * BLKW + col;
        ar[pos] = __bfloat162float(inr[g]);
        ai[pos] = __bfloat162float(ini[g]);
        float s, c;
        sincosf(6.283185307179586f * (float)pos / 1024.0f, &s, &c);  // conj
        twr[pos] = c; twi[pos] = s;
    }
    __syncthreads();

    float *pr = ar, *pi = ai, *qr = br, *qi = bi;
    #pragma unroll
    for (int p = 1; p <= 256; p <<= 2) {
        const int k = t & (p - 1);
        const int j = ((t - k) << 2) + k;
        const int a1 = k * (256 / p);
        float u0r = pr[t],       u0i = pi[t];
        float x1r = pr[t + 256], x1i = pi[t + 256];
        float x2r = pr[t + 512], x2i = pi[t + 512];
        float x3r = pr[t + 768], x3i = pi[t + 768];
        float w1r = twr[a1],     w1i = twi[a1];
        float w2r = twr[2 * a1], w2i = twi[2 * a1];
        float w3r = twr[3 * a1], w3i = twi[3 * a1];
        float u1r = x1r * w1r - x1i * w1i, u1i = x1r * w1i + x1i * w1r;
        float u2r = x2r * w2r - x2i * w2i, u2i = x2r * w2i + x2i * w2r;
        float u3r = x3r * w3r - x3i * w3i, u3i = x3r * w3i + x3i * w3r;
        float v0r = u0r + u2r, v0i = u0i + u2i;
        float v1r = u0r - u2r, v1i = u0i - u2i;
        float v2r = u1r + u3r, v2i = u1i + u3i;
        float v3r = u3i - u1i, v3i = u1r - u3r;   // +i*(u1-u3)
        __syncthreads();
        qr[j]         = v0r + v2r;  qi[j]         = v0i + v2i;
        qr[j + p]     = v1r + v3r;  qi[j + p]     = v1i + v3i;
        qr[j + 2 * p] = v0r - v2r;  qi[j + 2 * p] = v0i - v2i;
        qr[j + 3 * p] = v1r - v3r;  qi[j + 3 * p] = v1i - v3i;
        __syncthreads();
        float* tp;
        tp = pr; pr = qr; qr = tp;
        tp = pi; pi = qi; qi = tp;
    }

    #pragma unroll
    for (int q = 0; q < 4; q++) {
        int pos = t + 256 * q;
        size_t g = row * CCH + pos;
        out[g] = pr[pos] * INV_SQRTC + xres[g];
    }
}

// ------------------------- HMMA MLP layer ------------------------------------
__device__ __forceinline__ float softshrink_f(float v) {
    return (v > LAMBDA_F) ? (v - LAMBDA_F) : ((v < -LAMBDA_F) ? (v + LAMBDA_F) : 0.0f);
}

__device__ __forceinline__ void mma16816(float* d, const uint32_t* a, const uint32_t* b) {
    asm volatile(
        "mma.sync.aligned.m16n8k16.row.col.f32.bf16.bf16.f32 "
        "{%0,%1,%2,%3}, {%4,%5,%6,%7}, {%8,%9}, {%0,%1,%2,%3};"
        : "+f"(d[0]), "+f"(d[1]), "+f"(d[2]), "+f"(d[3])
        : "r"(a[0]), "r"(a[1]), "r"(a[2]), "r"(a[3]), "r"(b[0]), "r"(b[1]));
}

// grid (ROWS/128, NB), 256 threads (8 warps), 1 CTA/SM.
// smem: 4 tiles of 128 x KPAD bf16 + 2 x 128 fp32 bias.
#define SM_TILE_H   (128 * KPAD)                  // halves per tile
#define SM_BYTES    (4 * SM_TILE_H * 2 + 2 * 128 * 4)

template <bool RELU, bool SHRINK>
__global__ __launch_bounds__(256, 1) void mma_mlp_kernel(
        const __nv_bfloat16* __restrict__ Xr, const __nv_bfloat16* __restrict__ Xi,
        const __nv_bfloat16* __restrict__ Wr, const __nv_bfloat16* __restrict__ Wi,
        const float* __restrict__ Bg,
        __nv_bfloat16* __restrict__ Or, __nv_bfloat16* __restrict__ Oi) {
    extern __shared__ __nv_bfloat16 sm[];
    __nv_bfloat16* sXr = sm;
    __nv_bfloat16* sXi = sXr + SM_TILE_H;
    __nv_bfloat16* sWr = sXi + SM_TILE_H;
    __nv_bfloat16* sWi = sWr + SM_TILE_H;
    float* sBr = (float*)(sWi + SM_TILE_H);
    float* sBi = sBr + 128;

    const int tid  = threadIdx.x;
    const int lane = tid & 31;
    const int wid  = tid >> 5;
    const int blk  = blockIdx.y;
    const int m0   = blockIdx.x * 128;

    // ---- stage tiles (uint4 global load -> padded smem) ----
    const __nv_bfloat16* gXr = Xr + ((size_t)blk * ROWS + m0) * BLKW;
    const __nv_bfloat16* gXi = Xi + ((size_t)blk * ROWS + m0) * BLKW;
    const __nv_bfloat16* gWr = Wr + (size_t)blk * BLKW * BLKW;
    const __nv_bfloat16* gWi = Wi + (size_t)blk * BLKW * BLKW;
    #pragma unroll
    for (int it = 0; it < 8; it++) {
        int idx = tid + it * 256;                 // 0..2047 : 16B chunks
        int row = idx >> 4, c = idx & 15;
        *(uint4*)(sXr + row * KPAD + c * 8) = *(const uint4*)(gXr + row * BLKW + c * 8);
        *(uint4*)(sXi + row * KPAD + c * 8) = *(const uint4*)(gXi + row * BLKW + c * 8);
        *(uint4*)(sWr + row * KPAD + c * 8) = *(const uint4*)(gWr + row * BLKW + c * 8);
        *(uint4*)(sWi + row * KPAD + c * 8) = *(const uint4*)(gWi + row * BLKW + c * 8);
    }
    if (tid < BLKW) {
        sBr[tid] = Bg[blk * BLKW + tid];
        sBi[tid] = Bg[NB * BLKW + blk * BLKW + tid];
    }
    __syncthreads();

    const int wm = wid & 3;      // row group (32 rows)
    const int wn = wid >> 2;     // col group (64 cols)
    const int arow = wm * 32 + (lane >> 2);
    const int kq = (lane & 3) * 2;

    #pragma unroll
    for (int pass = 0; pass < 2; pass++) {
        const int n_base = wn * 64 + pass * 32;
        const int bn = n_base + (lane >> 2);

        float accR[2][4][4], accI[2][4][4];
        #pragma unroll
        for (int mi = 0; mi < 2; mi++)
            #pragma unroll
            for (int ni = 0; ni < 4; ni++)
                #pragma unroll
                for (int q = 0; q < 4; q++) { accR[mi][ni][q] = 0.0f; accI[mi][ni][q] = 0.0f; }

        #pragma unroll
        for (int ks = 0; ks < 8; ks++) {
            const int k0 = ks * 16;
            uint32_t axr[2][4], axi[2][4], axni[2][4];
            #pragma unroll
            for (int mi = 0; mi < 2; mi++) {
                const int r0 = arow + mi * 16;
                axr[mi][0] = *(const uint32_t*)(sXr + (r0)     * KPAD + k0 + kq);
                axr[mi][1] = *(const uint32_t*)(sXr + (r0 + 8) * KPAD + k0 + kq);
                axr[mi][2] = *(const uint32_t*)(sXr + (r0)     * KPAD + k0 + kq + 8);
                axr[mi][3] = *(const uint32_t*)(sXr + (r0 + 8) * KPAD + k0 + kq + 8);
                axi[mi][0] = *(const uint32_t*)(sXi + (r0)     * KPAD + k0 + kq);
                axi[mi][1] = *(const uint32_t*)(sXi + (r0 + 8) * KPAD + k0 + kq);
                axi[mi][2] = *(const uint32_t*)(sXi + (r0)     * KPAD + k0 + kq + 8);
                axi[mi][3] = *(const uint32_t*)(sXi + (r0 + 8) * KPAD + k0 + kq + 8);
                #pragma unroll
                for (int q = 0; q < 4; q++) axni[mi][q] = axi[mi][q] ^ 0x80008000u;
            }
            uint32_t bwr[4][2], bwi[4][2];
            #pragma unroll
            for (int ni = 0; ni < 4; ni++) {
                const int n = bn + ni * 8;
                bwr[ni][0] = *(const uint32_t*)(sWr + n * KPAD + k0 + kq);
                bwr[ni][1] = *(const uint32_t*)(sWr + n * KPAD + k0 + kq + 8);
                bwi[ni][0] = *(const uint32_t*)(sWi + n * KPAD + k0 + kq);
                bwi[ni][1] = *(const uint32_t*)(sWi + n * KPAD + k0 + kq + 8);
            }
            #pragma unroll
            for (int mi = 0; mi < 2; mi++)
                #pragma unroll
                for (int ni = 0; ni < 4; ni++) {
                    mma16816(accR[mi][ni], axr[mi],  bwr[ni]);   // + Xr*Wr
                    mma16816(accR[mi][ni], axni[mi], bwi[ni]);   // - Xi*Wi
                    mma16816(accI[mi][ni], axi[mi],  bwr[ni]);   // + Xi*Wr
                    mma16816(accI[mi][ni], axr[mi],  bwi[ni]);   // + Xr*Wi
                }
        }

        // ---- epilogue ----
        #pragma unroll
        for (int mi = 0; mi < 2; mi++) {
            #pragma unroll
            for (int ni = 0; ni < 4; ni++) {
                const int col = n_base + ni * 8 + (lane & 3) * 2;
                const int rgl = m0 + wm * 32 + mi * 16 + (lane >> 2);
                const float br0 = sBr[col], br1 = sBr[col + 1];
                const float bi0 = sBi[col], bi1 = sBi[col + 1];
                #pragma unroll
                for (int half = 0; half < 2; half++) {      // d0/d1 then d2/d3 (row+8)
                    float vr0 = accR[mi][ni][half * 2]     + br0;
                    float vr1 = accR[mi][ni][half * 2 + 1] + br1;
                    float vi0 = accI[mi][ni][half * 2]     + bi0;
                    float vi1 = accI[mi][ni][half * 2 + 1] + bi1;
                    if (RELU) {
                        vr0 = fmaxf(vr0, 0.0f); vr1 = fmaxf(vr1, 0.0f);
                        vi0 = fmaxf(vi0, 0.0f); vi1 = fmaxf(vi1, 0.0f);
                    }
                    if (SHRINK) {
                        vr0 = softshrink_f(vr0); vr1 = softshrink_f(vr1);
                        vi0 = softshrink_f(vi0); vi1 = softshrink_f(vi1);
                    }
                    __nv_bfloat162 pr2 = __floats2bfloat162_rn(vr0, vr1);
                    __nv_bfloat162 pi2 = __floats2bfloat162_rn(vi0, vi1);
                    const size_t g = ((size_t)blk * ROWS + rgl + half * 8) * BLKW + col;
                    *(__nv_bfloat162*)(Or + g) = pr2;
                    *(__nv_bfloat162*)(Oi + g) = pi2;
                }
            }
        }
    }
}

// -----------------------------------------------------------------------------
extern "C" void kernel_launch(void* const* d_in, const int* in_sizes, int n_in,
                              void* d_out, int out_size) {
    (void)in_sizes; (void)n_in; (void)out_size;
    const float* x  = (const float*)d_in[0];
    const float* w1 = (const float*)d_in[1];
    const float* b1 = (const float*)d_in[2];
    const float* w2 = (const float*)d_in[3];
    const float* b2 = (const float*)d_in[4];
    float* out = (float*)d_out;

    __nv_bfloat16 *xr, *xi, *o1r, *o1i, *w1r, *w1i, *w2r, *w2i;
    cudaGetSymbolAddress((void**)&xr,  g_xr);
    cudaGetSymbolAddress((void**)&xi,  g_xi);
    cudaGetSymbolAddress((void**)&o1r, g_o1r);
    cudaGetSymbolAddress((void**)&o1i, g_o1i);
    cudaGetSymbolAddress((void**)&w1r, g_w1r);
    cudaGetSymbolAddress((void**)&w1i, g_w1i);
    cudaGetSymbolAddress((void**)&w2r, g_w2r);
    cudaGetSymbolAddress((void**)&w2i, g_w2i);

    cudaFuncSetAttribute(mma_mlp_kernel<true, false>,
                         cudaFuncAttributeMaxDynamicSharedMemorySize, SM_BYTES);
    cudaFuncSetAttribute(mma_mlp_kernel<false, true>,
                         cudaFuncAttributeMaxDynamicSharedMemorySize, SM_BYTES);

    convert_weights<<<(NB * BLKW * BLKW + 255) / 256, 256>>>(w1, w2, w1r, w1i, w2r, w2i);

    fft_fwd_kernel<<<ROWS, 256>>>(x, xr, xi);

    dim3 grid(ROWS / 128, NB);
    mma_mlp_kernel<true, false><<<grid, 256, SM_BYTES>>>(xr, xi, w1r, w1i, b1, o1r, o1i);
    mma_mlp_kernel<false, true><<<grid, 256, SM_BYTES>>>(o1r, o1i, w2r, w2i, b2, xr, xi);

    fft_inv_kernel<<<ROWS, 256>>>(xr, xi, x, out);
}

// round 5
// speedup vs baseline: 3.7695x; 1.3157x over previous
#include <cuda_runtime.h>
#include <cuda_bf16.h>
#include <math.h>
#include <stdint.h>

#define ROWS      32768
#define CCH       1024
#define NB        8
#define BLKW      128
#define KPAD      136            // padded halves per smem row (272 B)
#define LAMBDA_F  0.01f
#define INV_SQRTC (1.0f / 32.0f)

// ------------------------- scratch (device globals) -------------------------
__device__ __align__(128) __nv_bfloat16 g_xr [(size_t)NB * ROWS * BLKW]; // blocked [blk][row][128]
__device__ __align__(128) __nv_bfloat16 g_xi [(size_t)NB * ROWS * BLKW];
__device__ __align__(128) __nv_bfloat16 g_o1r[(size_t)NB * ROWS * BLKW];
__device__ __align__(128) __nv_bfloat16 g_o1i[(size_t)NB * ROWS * BLKW];
__device__ __align__(128) __nv_bfloat16 g_w1r[NB * BLKW * BLKW];
__device__ __align__(128) __nv_bfloat16 g_w1i[NB * BLKW * BLKW];
__device__ __align__(128) __nv_bfloat16 g_w2r[NB * BLKW * BLKW];
__device__ __align__(128) __nv_bfloat16 g_w2i[NB * BLKW * BLKW];
__device__ float g_gtwr[CCH];
__device__ float g_gtwi[CCH];

// ------------------------- setup kernels -------------------------------------
__global__ void setup_twiddles(float* twr, float* twi) {
    int i = blockIdx.x * blockDim.x + threadIdx.x;
    if (i < CCH) {
        float s, c;
        sincosf(-6.283185307179586f * (float)i / (float)CCH, &s, &c);
        twr[i] = c; twi[i] = s;
    }
}

__global__ void convert_weights(const float* __restrict__ w1,
                                const float* __restrict__ w2,
                                __nv_bfloat16* __restrict__ W1r, __nv_bfloat16* __restrict__ W1i,
                                __nv_bfloat16* __restrict__ W2r, __nv_bfloat16* __restrict__ W2i) {
    int idx = blockIdx.x * blockDim.x + threadIdx.x;   // dst layout [blk][n][k]
    if (idx >= NB * BLKW * BLKW) return;
    int blk = idx >> 14;
    int n   = (idx >> 7) & 127;
    int k   = idx & 127;
    size_t src = (size_t)blk * (BLKW * BLKW) + (size_t)k * BLKW + n;  // w[.][blk][k][n]
    W1r[idx] = __float2bfloat16(w1[src]);
    W1i[idx] = __float2bfloat16(w1[(size_t)NB * BLKW * BLKW + src]);
    W2r[idx] = __float2bfloat16(w2[src]);
    W2i[idx] = __float2bfloat16(w2[(size_t)NB * BLKW * BLKW + src]);
}

// ------------------------- radix-4 Stockham core ------------------------------
// one stage set, 256 threads, in smem ping-pong. Twiddles in twr/twi (full-size
// table of e^{-2pi i t/1024}; inverse passes negated twi).
#define FFT_STAGES(pr, pi, qr, qi, twr, twi)                                    \
    _Pragma("unroll")                                                           \
    for (int p = 1; p <= 256; p <<= 2) {                                        \
        const int k = t & (p - 1);                                              \
        const int j = ((t - k) << 2) + k;                                       \
        const int a1 = k * (256 / p);                                           \
        float u0r = pr[t],       u0i = pi[t];                                   \
        float x1r = pr[t + 256], x1i = pi[t + 256];                             \
        float x2r = pr[t + 512], x2i = pi[t + 512];                             \
        float x3r = pr[t + 768], x3i = pi[t + 768];                             \
        float w1r = twr[a1],     w1i = twi[a1];                                 \
        float w2r = twr[2 * a1], w2i = twi[2 * a1];                             \
        float w3r = twr[3 * a1], w3i = twi[3 * a1];                             \
        float u1r = x1r * w1r - x1i * w1i, u1i = x1r * w1i + x1i * w1r;         \
        float u2r = x2r * w2r - x2i * w2i, u2i = x2r * w2i + x2i * w2r;         \
        float u3r = x3r * w3r - x3i * w3i, u3i = x3r * w3i + x3i * w3r;         \
        float v0r = u0r + u2r, v0i = u0i + u2i;                                 \
        float v1r = u0r - u2r, v1i = u0i - u2i;                                 \
        float v2r = u1r + u3r, v2i = u1i + u3i;                                 \
        float v3r = DIRP(u1i - u3i), v3i = DIRP(u3r - u1r);                     \
        __syncthreads();                                                        \
        qr[j]         = v0r + v2r;  qi[j]         = v0i + v2i;                  \
        qr[j + p]     = v1r + v3r;  qi[j + p]     = v1i + v3i;                  \
        qr[j + 2 * p] = v0r - v2r;  qi[j + 2 * p] = v0i - v2i;                  \
        qr[j + 3 * p] = v1r - v3r;  qi[j + 3 * p] = v1i - v3i;                  \
        __syncthreads();                                                        \
        float* tp;                                                              \
        tp = pr; pr = qr; qr = tp;                                              \
        tp = pi; pi = qi; qi = tp;                                              \
    }

// forward: two real rows packed into one complex FFT
#define DIRP(v) (v)
__global__ __launch_bounds__(256) void fft_fwd_kernel(const float* __restrict__ x,
                                                      __nv_bfloat16* __restrict__ outr,
                                                      __nv_bfloat16* __restrict__ outi,
                                                      const float* __restrict__ gtwr,
                                                      const float* __restrict__ gtwi) {
    __shared__ float ar[CCH], ai[CCH], br[CCH], bi[CCH];
    __shared__ float twr[CCH], twi[CCH];
    const int t = threadIdx.x;
    const size_t rowa = (size_t)blockIdx.x * 2;
    const float* xa = x + rowa * CCH;
    const float* xb = xa + CCH;

    #pragma unroll
    for (int q = 0; q < 4; q++) {
        int pos = t + 256 * q;
        ar[pos] = xa[pos] * INV_SQRTC;
        ai[pos] = xb[pos] * INV_SQRTC;
        twr[pos] = gtwr[pos];
        twi[pos] = gtwi[pos];
    }
    __syncthreads();

    float *pr = ar, *pi = ai, *qr = br, *qi = bi;
    FFT_STAGES(pr, pi, qr, qi, twr, twi)

    // unpack: A = (Z[k]+conj(Z[-k]))/2 -> row a ; B = (Z[k]-conj(Z[-k]))/2i -> row b
    #pragma unroll
    for (int q = 0; q < 4; q++) {
        int pos = t + 256 * q;
        int nk = (CCH - pos) & (CCH - 1);
        float zr = pr[pos], zi = pi[pos];
        float wr = pr[nk],  wi = pi[nk];
        float Ar = 0.5f * (zr + wr), Ai = 0.5f * (zi - wi);
        float Br = 0.5f * (zi + wi), Bi = 0.5f * (wr - zr);
        int blk = pos >> 7, col = pos & 127;
        size_t ga = ((size_t)blk * ROWS + rowa) * BLKW + col;
        outr[ga] = __float2bfloat16(Ar);
        outi[ga] = __float2bfloat16(Ai);
        outr[ga + BLKW] = __float2bfloat16(Br);
        outi[ga + BLKW] = __float2bfloat16(Bi);
    }
}
#undef DIRP

// inverse: Hermitian-symmetrize two spectra, pack, one IFFT -> two real rows
#define DIRP(v) (-(v))
__global__ __launch_bounds__(256) void fft_inv_kernel(const __nv_bfloat16* __restrict__ inr,
                                                      const __nv_bfloat16* __restrict__ ini,
                                                      const float* __restrict__ xres,
                                                      float* __restrict__ out,
                                                      const float* __restrict__ gtwr,
                                                      const float* __restrict__ gtwi) {
    __shared__ float yar[CCH], yai[CCH], ybr[CCH], ybi[CCH];
    __shared__ float ar[CCH], ai[CCH];
    __shared__ float twr[CCH], twi[CCH];
    const int t = threadIdx.x;
    const size_t rowa = (size_t)blockIdx.x * 2;

    #pragma unroll
    for (int q = 0; q < 4; q++) {
        int pos = t + 256 * q;
        int blk = pos >> 7, col = pos & 127;
        size_t ga = ((size_t)blk * ROWS + rowa) * BLKW + col;
        yar[pos] = __bfloat162float(inr[ga]);
        yai[pos] = __bfloat162float(ini[ga]);
        ybr[pos] = __bfloat162float(inr[ga + BLKW]);
        ybi[pos] = __bfloat162float(ini[ga + BLKW]);
        twr[pos] = gtwr[pos];
        twi[pos] = gtwi[pos];     // DIRP negates the -i factor in the butterfly
    }
    __syncthreads();

    // A = Herm(Ya), B = Herm(Yb); z_in = A + iB
    #pragma unroll
    for (int q = 0; q < 4; q++) {
        int pos = t + 256 * q;
        int nk = (CCH - pos) & (CCH - 1);
        float Ar = 0.5f * (yar[pos] + yar[nk]);
        float Ai = 0.5f * (yai[pos] - yai[nk]);
        float Br = 0.5f * (ybr[pos] + ybr[nk]);
        float Bi = 0.5f * (ybi[pos] - ybi[nk]);
        ar[pos] = Ar - Bi;
        ai[pos] = Ai + Br;
    }
    __syncthreads();

    // IFFT with conj twiddles: negate twi on use via a custom stage loop
    float *pr = ar, *pi = ai, *qr = yar, *qi = yai;
    #pragma unroll
    for (int p = 1; p <= 256; p <<= 2) {
        const int k = t & (p - 1);
        const int j = ((t - k) << 2) + k;
        const int a1 = k * (256 / p);
        float u0r = pr[t],       u0i = pi[t];
        float x1r = pr[t + 256], x1i = pi[t + 256];
        float x2r = pr[t + 512], x2i = pi[t + 512];
        float x3r = pr[t + 768], x3i = pi[t + 768];
        float w1r = twr[a1],     w1i = -twi[a1];
        float w2r = twr[2 * a1], w2i = -twi[2 * a1];
        float w3r = twr[3 * a1], w3i = -twi[3 * a1];
        float u1r = x1r * w1r - x1i * w1i, u1i = x1r * w1i + x1i * w1r;
        float u2r = x2r * w2r - x2i * w2i, u2i = x2r * w2i + x2i * w2r;
        float u3r = x3r * w3r - x3i * w3i, u3i = x3r * w3i + x3i * w3r;
        float v0r = u0r + u2r, v0i = u0i + u2i;
        float v1r = u0r - u2r, v1i = u0i - u2i;
        float v2r = u1r + u3r, v2i = u1i + u3i;
        float v3r = u3i - u1i, v3i = u1r - u3r;   // +i*(u1-u3)
        __syncthreads();
        qr[j]         = v0r + v2r;  qi[j]         = v0i + v2i;
        qr[j + p]     = v1r + v3r;  qi[j + p]     = v1i + v3i;
        qr[j + 2 * p] = v0r - v2r;  qi[j + 2 * p] = v0i - v2i;
        qr[j + 3 * p] = v1r - v3r;  qi[j + 3 * p] = v1i - v3i;
        __syncthreads();
        float* tp;
        tp = pr; pr = qr; qr = tp;
        tp = pi; pi = qi; qi = tp;
    }

    #pragma unroll
    for (int q = 0; q < 4; q++) {
        int pos = t + 256 * q;
        size_t ga = rowa * CCH + pos;
        out[ga]       = pr[pos] * INV_SQRTC + xres[ga];
        out[ga + CCH] = pi[pos] * INV_SQRTC + xres[ga + CCH];
    }
}
#undef DIRP

// ------------------------- HMMA MLP layer ------------------------------------
__device__ __forceinline__ float softshrink_f(float v) {
    return (v > LAMBDA_F) ? (v - LAMBDA_F) : ((v < -LAMBDA_F) ? (v + LAMBDA_F) : 0.0f);
}
__device__ __forceinline__ uint32_t smem_u32(const void* p) {
    uint32_t a;
    asm("{ .reg .u64 t; cvta.to.shared.u64 t, %1; cvt.u32.u64 %0, t; }" : "=r"(a) : "l"(p));
    return a;
}
__device__ __forceinline__ void mma16816(float* d, const uint32_t* a, const uint32_t* b) {
    asm volatile(
        "mma.sync.aligned.m16n8k16.row.col.f32.bf16.bf16.f32 "
        "{%0,%1,%2,%3}, {%4,%5,%6,%7}, {%8,%9}, {%0,%1,%2,%3};"
        : "+f"(d[0]), "+f"(d[1]), "+f"(d[2]), "+f"(d[3])
        : "r"(a[0]), "r"(a[1]), "r"(a[2]), "r"(a[3]), "r"(b[0]), "r"(b[1]));
}
__device__ __forceinline__ void ldm_x4(uint32_t* r, uint32_t addr) {
    asm volatile("ldmatrix.sync.aligned.m8n8.x4.shared.b16 {%0,%1,%2,%3}, [%4];"
        : "=r"(r[0]), "=r"(r[1]), "=r"(r[2]), "=r"(r[3]) : "r"(addr));
}
__device__ __forceinline__ void ldm_x2(uint32_t* r, uint32_t addr) {
    asm volatile("ldmatrix.sync.aligned.m8n8.x2.shared.b16 {%0,%1}, [%2];"
        : "=r"(r[0]), "=r"(r[1]) : "r"(addr));
}

// grid (ROWS/64, NB), 256 threads (8 warps), 2 CTAs/SM.
// smem: X tiles 64xKPAD x2, W tiles 128xKPAD x2, biases.
#define SM_X_H    (64 * KPAD)
#define SM_W_H    (128 * KPAD)
#define SM_BYTES  ((2 * SM_X_H + 2 * SM_W_H) * 2 + 2 * 128 * 4)

template <bool RELU, bool SHRINK>
__global__ __launch_bounds__(256, 2) void mma_mlp_kernel(
        const __nv_bfloat16* __restrict__ Xr, const __nv_bfloat16* __restrict__ Xi,
        const __nv_bfloat16* __restrict__ Wr, const __nv_bfloat16* __restrict__ Wi,
        const float* __restrict__ Bg,
        __nv_bfloat16* __restrict__ Or, __nv_bfloat16* __restrict__ Oi) {
    extern __shared__ __nv_bfloat16 sm[];
    __nv_bfloat16* sXr = sm;
    __nv_bfloat16* sXi = sXr + SM_X_H;
    __nv_bfloat16* sWr = sXi + SM_X_H;
    __nv_bfloat16* sWi = sWr + SM_W_H;
    float* sBr = (float*)(sWi + SM_W_H);
    float* sBi = sBr + 128;

    const int tid  = threadIdx.x;
    const int lane = tid & 31;
    const int wid  = tid >> 5;
    const int blk  = blockIdx.y;
    const int m0   = blockIdx.x * 64;

    // ---- stage tiles ----
    const __nv_bfloat16* gXr = Xr + ((size_t)blk * ROWS + m0) * BLKW;
    const __nv_bfloat16* gXi = Xi + ((size_t)blk * ROWS + m0) * BLKW;
    const __nv_bfloat16* gWr = Wr + (size_t)blk * BLKW * BLKW;
    const __nv_bfloat16* gWi = Wi + (size_t)blk * BLKW * BLKW;
    #pragma unroll
    for (int it = 0; it < 4; it++) {
        int idx = tid + it * 256;                 // 0..1023 : 16B chunks (64 rows)
        int row = idx >> 4, c = idx & 15;
        *(uint4*)(sXr + row * KPAD + c * 8) = *(const uint4*)(gXr + row * BLKW + c * 8);
        *(uint4*)(sXi + row * KPAD + c * 8) = *(const uint4*)(gXi + row * BLKW + c * 8);
    }
    #pragma unroll
    for (int it = 0; it < 8; it++) {
        int idx = tid + it * 256;                 // 0..2047 (128 rows)
        int row = idx >> 4, c = idx & 15;
        *(uint4*)(sWr + row * KPAD + c * 8) = *(const uint4*)(gWr + row * BLKW + c * 8);
        *(uint4*)(sWi + row * KPAD + c * 8) = *(const uint4*)(gWi + row * BLKW + c * 8);
    }
    if (tid < BLKW) {
        sBr[tid] = Bg[blk * BLKW + tid];
        sBi[tid] = Bg[NB * BLKW + blk * BLKW + tid];
    }
    __syncthreads();

    const int wm = wid & 3;      // 16-row group
    const int wn = wid >> 2;     // 64-col group

    // ldmatrix per-lane byte offsets
    const int grp = lane >> 3;
    const int rA  = wm * 16 + (lane & 7) + ((grp & 1) << 3);
    const int kA  = (grp >> 1) << 3;
    const uint32_t offA = (uint32_t)(rA * KPAD + kA) * 2;
    const uint32_t offB = (uint32_t)((lane & 7) * KPAD + ((lane >> 3) & 1) * 8) * 2;
    const uint32_t baseXr = smem_u32(sXr), baseXi = smem_u32(sXi);
    const uint32_t baseWr = smem_u32(sWr), baseWi = smem_u32(sWi);

    #pragma unroll
    for (int pass = 0; pass < 2; pass++) {
        const int n_base = wn * 64 + pass * 32;

        float accR[4][4], accI[4][4];
        #pragma unroll
        for (int ni = 0; ni < 4; ni++)
            #pragma unroll
            for (int q = 0; q < 4; q++) { accR[ni][q] = 0.0f; accI[ni][q] = 0.0f; }

        #pragma unroll
        for (int ks = 0; ks < 8; ks++) {
            const uint32_t kb = (uint32_t)(ks * 16) * 2;   // byte offset along k
            uint32_t axr[4], axi[4], axni[4];
            ldm_x4(axr, baseXr + offA + kb);
            ldm_x4(axi, baseXi + offA + kb);
            #pragma unroll
            for (int q = 0; q < 4; q++) axni[q] = axi[q] ^ 0x80008000u;

            uint32_t bwr[4][2], bwi[4][2];
            #pragma unroll
            for (int ni = 0; ni < 4; ni++) {
                const uint32_t nb = (uint32_t)((n_base + ni * 8) * KPAD) * 2;
                ldm_x2(bwr[ni], baseWr + nb + offB + kb);
                ldm_x2(bwi[ni], baseWi + nb + offB + kb);
            }
            #pragma unroll
            for (int ni = 0; ni < 4; ni++) {
                mma16816(accR[ni], axr,  bwr[ni]);   // + Xr*Wr
                mma16816(accR[ni], axni, bwi[ni]);   // - Xi*Wi
                mma16816(accI[ni], axi,  bwr[ni]);   // + Xi*Wr
                mma16816(accI[ni], axr,  bwi[ni]);   // + Xr*Wi
            }
        }

        // ---- epilogue ----
        #pragma unroll
        for (int ni = 0; ni < 4; ni++) {
            const int col = n_base + ni * 8 + (lane & 3) * 2;
            const int row = m0 + wm * 16 + (lane >> 2);
            const float br0 = sBr[col], br1 = sBr[col + 1];
            const float bi0 = sBi[col], bi1 = sBi[col + 1];
            #pragma unroll
            for (int half = 0; half < 2; half++) {
                float vr0 = accR[ni][half * 2]     + br0;
                float vr1 = accR[ni][half * 2 + 1] + br1;
                float vi0 = accI[ni][half * 2]     + bi0;
                float vi1 = accI[ni][half * 2 + 1] + bi1;
                if (RELU) {
                    vr0 = fmaxf(vr0, 0.0f); vr1 = fmaxf(vr1, 0.0f);
                    vi0 = fmaxf(vi0, 0.0f); vi1 = fmaxf(vi1, 0.0f);
                }
                if (SHRINK) {
                    vr0 = softshrink_f(vr0); vr1 = softshrink_f(vr1);
                    vi0 = softshrink_f(vi0); vi1 = softshrink_f(vi1);
                }
                __nv_bfloat162 pr2 = __floats2bfloat162_rn(vr0, vr1);
                __nv_bfloat162 pi2 = __floats2bfloat162_rn(vi0, vi1);
                const size_t g = ((size_t)blk * ROWS + row + half * 8) * BLKW + col;
                *(__nv_bfloat162*)(Or + g) = pr2;
                *(__nv_bfloat162*)(Oi + g) = pi2;
            }
        }
    }
}

// -----------------------------------------------------------------------------
extern "C" void kernel_launch(void* const* d_in, const int* in_sizes, int n_in,
                              void* d_out, int out_size) {
    (void)in_sizes; (void)n_in; (void)out_size;
    const float* x  = (const float*)d_in[0];
    const float* w1 = (const float*)d_in[1];
    const float* b1 = (const float*)d_in[2];
    const float* w2 = (const float*)d_in[3];
    const float* b2 = (const float*)d_in[4];
    float* out = (float*)d_out;

    __nv_bfloat16 *xr, *xi, *o1r, *o1i, *w1r, *w1i, *w2r, *w2i;
    float *gtwr, *gtwi;
    cudaGetSymbolAddress((void**)&xr,  g_xr);
    cudaGetSymbolAddress((void**)&xi,  g_xi);
    cudaGetSymbolAddress((void**)&o1r, g_o1r);
    cudaGetSymbolAddress((void**)&o1i, g_o1i);
    cudaGetSymbolAddress((void**)&w1r, g_w1r);
    cudaGetSymbolAddress((void**)&w1i, g_w1i);
    cudaGetSymbolAddress((void**)&w2r, g_w2r);
    cudaGetSymbolAddress((void**)&w2i, g_w2i);
    cudaGetSymbolAddress((void**)&gtwr, g_gtwr);
    cudaGetSymbolAddress((void**)&gtwi, g_gtwi);

    cudaFuncSetAttribute(mma_mlp_kernel<true, false>,
                         cudaFuncAttributeMaxDynamicSharedMemorySize, SM_BYTES);
    cudaFuncSetAttribute(mma_mlp_kernel<false, true>,
                         cudaFuncAttributeMaxDynamicSharedMemorySize, SM_BYTES);

    setup_twiddles<<<4, 256>>>(gtwr, gtwi);
    convert_weights<<<(NB * BLKW * BLKW + 255) / 256, 256>>>(w1, w2, w1r, w1i, w2r, w2i);

    fft_fwd_kernel<<<ROWS / 2, 256>>>(x, xr, xi, gtwr, gtwi);

    dim3 grid(ROWS / 64, NB);
    mma_mlp_kernel<true, false><<<grid, 256, SM_BYTES>>>(xr, xi, w1r, w1i, b1, o1r, o1i);
    mma_mlp_kernel<false, true><<<grid, 256, SM_BYTES>>>(o1r, o1i, w2r, w2i, b2, xr, xi);

    fft_inv_kernel<<<ROWS / 2, 256>>>(xr, xi, x, out, gtwr, gtwi);
}